// round 1
// baseline (speedup 1.0000x reference)
#include <cuda_runtime.h>
#include <cuda_bf16.h>
#include <cstdint>

// PairExcludeMask: out[f,i,n] = type_mask[ atype[f,i]*(ntypes+1) + tj ]
//   where tj = (nlist[f,i,n] == -1) ? ntypes : atype[f, nlist[f,i,n]]
//
// Shapes (fixed by dataset):
//   nlist:     [4, 16384, 128] int32
//   atype_ext: [4, 32768]      int32
//   type_mask: [81]            float32   ((ntypes+1)^2, ntypes=8)
//   out:       [4, 16384, 128] float32

static constexpr int NF    = 4;
static constexpr int NLOC  = 16384;
static constexpr int NNEI  = 128;
static constexpr int NALL  = 32768;
static constexpr int NTYPES = 8;
static constexpr int TM1   = NTYPES + 1;          // 9
static constexpr int TABLE = TM1 * TM1;           // 81

static constexpr int VEC        = 4;              // int4 / float4
static constexpr int TOTAL      = NF * NLOC * NNEI;           // 8,388,608
static constexpr int TOTAL_VEC  = TOTAL / VEC;                 // 2,097,152
static constexpr int ROW_VEC    = NNEI / VEC;                  // 32 vec-elems per (f,i) row
static constexpr int THREADS    = 256;
static constexpr int BLOCKS     = TOTAL_VEC / THREADS;         // 8192

__global__ __launch_bounds__(THREADS)
void pair_exclude_mask_kernel(const int4* __restrict__ nlist4,
                              const int*  __restrict__ atype,
                              const float* __restrict__ tmask,
                              float4* __restrict__ out4)
{
    __shared__ float s_mask[TABLE];
    if (threadIdx.x < TABLE) s_mask[threadIdx.x] = tmask[threadIdx.x];
    __syncthreads();

    int t = blockIdx.x * THREADS + threadIdx.x;   // vec index, < TOTAL_VEC

    int row = t >> 5;                              // / ROW_VEC (32)
    int f   = row >> 14;                           // / NLOC (16384)
    int i   = row & (NLOC - 1);

    const int* __restrict__ at = atype + f * NALL;

    // type_i * (ntypes+1); broadcast within the 8 threads sharing the row -> L1 hit
    int ti = __ldg(&at[i]) * TM1;

    int4 nj = nlist4[t];

    // 4 independent L2-resident gathers (random into 128KB) -> MLP hides latency
    int tj0 = (nj.x < 0) ? NTYPES : __ldg(&at[nj.x]);
    int tj1 = (nj.y < 0) ? NTYPES : __ldg(&at[nj.y]);
    int tj2 = (nj.z < 0) ? NTYPES : __ldg(&at[nj.z]);
    int tj3 = (nj.w < 0) ? NTYPES : __ldg(&at[nj.w]);

    float4 r;
    r.x = s_mask[ti + tj0];
    r.y = s_mask[ti + tj1];
    r.z = s_mask[ti + tj2];
    r.w = s_mask[ti + tj3];

    out4[t] = r;
}

extern "C" void kernel_launch(void* const* d_in, const int* in_sizes, int n_in,
                              void* d_out, int out_size)
{
    const int4*  nlist4 = (const int4*) d_in[0];
    const int*   atype  = (const int*)  d_in[1];
    const float* tmask  = (const float*)d_in[2];
    // d_in[3] = ntypes scalar (value 8, baked into constants above)

    float4* out4 = (float4*)d_out;

    pair_exclude_mask_kernel<<<BLOCKS, THREADS>>>(nlist4, atype, tmask, out4);
}

// round 2
// speedup vs baseline: 1.3848x; 1.3848x over previous
#include <cuda_runtime.h>
#include <cuda_bf16.h>
#include <cstdint>

// PairExcludeMask: out[f,i,n] = type_mask[ atype[f,i]*9 + tj ]
//   tj = (nlist[f,i,n] == -1) ? 8 : atype[f, nlist[f,i,n]]
//
// Strategy: per-frame SMEM table s_w[j] (uint16 bitfield over ti) so each
// neighbor lookup is ONE shared-memory load + shift, instead of a random
// L1tex global gather + table lookup.
//
// Shapes fixed by dataset:
//   nlist [4,16384,128] i32, atype_ext [4,32768] i32, type_mask [81] f32,
//   out [4,16384,128] f32

static constexpr int NF     = 4;
static constexpr int NLOC   = 16384;
static constexpr int NNEI   = 128;
static constexpr int NALL   = 32768;
static constexpr int NTYPES = 8;
static constexpr int TM1    = NTYPES + 1;      // 9

static constexpr int THREADS       = 512;
static constexpr int BLOCKS_PER_F  = 64;
static constexpr int ROWS_PB       = NLOC / BLOCKS_PER_F;   // 256 rows / block
static constexpr int ROW_VEC       = NNEI / 4;              // 32 float4 per row
static constexpr int VEC_PB        = ROWS_PB * ROW_VEC;     // 8192 vec4 / block
static constexpr int BLOCKS        = NF * BLOCKS_PER_F;     // 256

// dynamic smem: uint16 w-table [NALL+2] + int ti-cache [ROWS_PB]
static constexpr int SMEM_W_BYTES  = (NALL + 2) * 2;        // 65540
static constexpr int SMEM_BYTES    = SMEM_W_BYTES + ROWS_PB * 4;  // 66564

__global__ __launch_bounds__(THREADS)
void pair_exclude_mask_kernel(const int4* __restrict__ nlist4,
                              const int*  __restrict__ atype,
                              const float* __restrict__ tmask,
                              float4* __restrict__ out4)
{
    extern __shared__ unsigned char smem[];
    uint16_t* s_w  = (uint16_t*)smem;                       // [NALL+1] (+pad)
    int*      s_ti = (int*)(smem + SMEM_W_BYTES);           // [ROWS_PB]
    __shared__ uint16_t s_tw[TM1];                          // per-type bit word

    const int tid  = threadIdx.x;
    const int f    = blockIdx.x >> 6;                       // / BLOCKS_PER_F
    const int row0 = (blockIdx.x & (BLOCKS_PER_F - 1)) * ROWS_PB;
    const int* __restrict__ at = atype + f * NALL;

    // --- per-type word: bit ti of s_tw[tj] = (tmask[ti*9+tj] != 0) ---
    if (tid < TM1) {
        unsigned w = 0;
        #pragma unroll
        for (int ti = 0; ti < TM1; ++ti)
            w |= (tmask[ti * TM1 + tid] != 0.0f ? 1u : 0u) << ti;
        s_tw[tid] = (uint16_t)w;
    }
    __syncthreads();

    // --- build per-atom word table in SMEM (coalesced int4 loads) ---
    const int4* __restrict__ at4 = (const int4*)at;
    #pragma unroll 4
    for (int j = tid; j < NALL / 4; j += THREADS) {
        int4 a = at4[j];
        unsigned long long pack =
              (unsigned long long)s_tw[a.x]
            | ((unsigned long long)s_tw[a.y] << 16)
            | ((unsigned long long)s_tw[a.z] << 32)
            | ((unsigned long long)s_tw[a.w] << 48);
        *(unsigned long long*)(s_w + 4 * j) = pack;
    }
    if (tid == 0) s_w[NALL] = s_tw[NTYPES];                 // virtual atom (-1)

    // --- cache this block's center types ---
    for (int r = tid; r < ROWS_PB; r += THREADS)
        s_ti[r] = at[row0 + r];
    __syncthreads();

    // --- main stream: 16 iterations of vec4 work per thread ---
    const size_t base = ((size_t)f * NLOC + row0) * ROW_VEC;
    const int4*  __restrict__ nl = nlist4 + base;
    float4*      __restrict__ ob = out4  + base;

    #pragma unroll 2
    for (int v = tid; v < VEC_PB; v += THREADS) {
        const int ti = s_ti[v >> 5];                        // warp-uniform
        int4 nj = nl[v];

        int j0 = (nj.x < 0) ? NALL : nj.x;
        int j1 = (nj.y < 0) ? NALL : nj.y;
        int j2 = (nj.z < 0) ? NALL : nj.z;
        int j3 = (nj.w < 0) ? NALL : nj.w;

        unsigned w0 = s_w[j0];
        unsigned w1 = s_w[j1];
        unsigned w2 = s_w[j2];
        unsigned w3 = s_w[j3];

        float4 r;
        r.x = ((w0 >> ti) & 1u) ? 1.0f : 0.0f;
        r.y = ((w1 >> ti) & 1u) ? 1.0f : 0.0f;
        r.z = ((w2 >> ti) & 1u) ? 1.0f : 0.0f;
        r.w = ((w3 >> ti) & 1u) ? 1.0f : 0.0f;

        ob[v] = r;
    }
}

extern "C" void kernel_launch(void* const* d_in, const int* in_sizes, int n_in,
                              void* d_out, int out_size)
{
    const int4*  nlist4 = (const int4*) d_in[0];
    const int*   atype  = (const int*)  d_in[1];
    const float* tmask  = (const float*)d_in[2];
    // d_in[3] = ntypes scalar (8, baked into constants)

    float4* out4 = (float4*)d_out;

    cudaFuncSetAttribute(pair_exclude_mask_kernel,
                         cudaFuncAttributeMaxDynamicSharedMemorySize,
                         SMEM_BYTES);

    pair_exclude_mask_kernel<<<BLOCKS, THREADS, SMEM_BYTES>>>(
        nlist4, atype, tmask, out4);
}

// round 3
// speedup vs baseline: 1.5668x; 1.1315x over previous
#include <cuda_runtime.h>
#include <cuda_bf16.h>
#include <cstdint>

// PairExcludeMask: out[f,i,n] = type_mask[ atype[f,i]*9 + tj ]
//   tj = (nlist[f,i,n] == -1) ? 8 : atype[f, nlist[f,i,n]]
//
// Two kernels:
//  1. pack_kernel: atype -> 4-bit-per-atom table in __device__ scratch (once)
//  2. mask_kernel: each block copies the 16KB nibble table into smem, then
//     streams nlist->out. Per neighbor: 1 random LDS.32 + nibble extract +
//     test against a warp-uniform 9-bit row word rw[ti].
//
// Shapes fixed by dataset:
//   nlist [4,16384,128] i32, atype_ext [4,32768] i32, type_mask [81] f32,
//   out [4,16384,128] f32

static constexpr int NF     = 4;
static constexpr int NLOC   = 16384;
static constexpr int NNEI   = 128;
static constexpr int NALL   = 32768;
static constexpr int NTYPES = 8;
static constexpr int TM1    = NTYPES + 1;          // 9

static constexpr int WORDS   = NALL / 8;           // 4096 packed words / frame
static constexpr int WORDS_P = WORDS + 8;          // + virtual atom word + pad

__device__ __align__(16) uint32_t g_pack[NF][WORDS_P];

// ---------------- kernel 1: pack types to nibbles ----------------
__global__ __launch_bounds__(256)
void pack_kernel(const int* __restrict__ atype)
{
    int idx = blockIdx.x * 256 + threadIdx.x;      // 0 .. NF*WORDS-1
    int f   = idx >> 12;                           // / WORDS (4096)
    int wi  = idx & (WORDS - 1);
    const int4* __restrict__ at4 = (const int4*)(atype + f * NALL);
    int4 a = at4[wi * 2];
    int4 b = at4[wi * 2 + 1];
    uint32_t p = (uint32_t)a.x        | ((uint32_t)a.y << 4)
               | ((uint32_t)a.z << 8) | ((uint32_t)a.w << 12)
               | ((uint32_t)b.x << 16)| ((uint32_t)b.y << 20)
               | ((uint32_t)b.z << 24)| ((uint32_t)b.w << 28);
    g_pack[f][wi] = p;
    if (wi == 0) {                                 // virtual atom j == NALL
        g_pack[f][WORDS] = (uint32_t)NTYPES;       // nibble 0 = type 8
        #pragma unroll
        for (int k = 1; k < 8; ++k) g_pack[f][WORDS + k] = 0;
    }
}

// ---------------- kernel 2: stream the mask ----------------
static constexpr int THREADS_B = 256;
static constexpr int BPF       = 256;                      // blocks per frame
static constexpr int ROWS_PB   = NLOC / BPF;               // 64
static constexpr int ROW_VEC   = NNEI / 4;                 // 32
static constexpr int VEC_PB    = ROWS_PB * ROW_VEC;        // 2048
static constexpr int ITERS     = VEC_PB / THREADS_B;       // 8
static constexpr int BLOCKS_B  = NF * BPF;                 // 1024

__global__ __launch_bounds__(THREADS_B)
void mask_kernel(const int4* __restrict__ nlist4,
                 const int*  __restrict__ atype,
                 const float* __restrict__ tmask,
                 float4* __restrict__ out4)
{
    __shared__ uint32_t s_nib[WORDS_P];            // 16.4 KB nibble table
    __shared__ uint32_t s_rw[TM1];                 // per-center-type row word

    const int tid  = threadIdx.x;
    const int f    = blockIdx.x >> 8;              // / BPF
    const int row0 = (blockIdx.x & (BPF - 1)) * ROWS_PB;

    // coalesced 16-byte copy of the packed table from L2
    {
        const uint4* __restrict__ src = (const uint4*)g_pack[f];
        uint4* dst = (uint4*)s_nib;
        #pragma unroll
        for (int k = tid; k < WORDS_P / 4; k += THREADS_B)
            dst[k] = src[k];
    }
    // rw[ti] bit tj = (type_mask[ti*9+tj] != 0)
    if (tid < TM1) {
        uint32_t w = 0;
        #pragma unroll
        for (int tj = 0; tj < TM1; ++tj)
            w |= (tmask[tid * TM1 + tj] != 0.0f ? 1u : 0u) << tj;
        s_rw[tid] = w;
    }
    __syncthreads();

    const int* __restrict__ at = atype + f * NALL;
    const size_t base = ((size_t)f * NLOC + row0) * ROW_VEC;
    const int4*  __restrict__ nl = nlist4 + base;
    float4*      __restrict__ ob = out4  + base;

    #pragma unroll
    for (int k = 0; k < ITERS; ++k) {
        const int v = tid + k * THREADS_B;
        // one row per warp (32 consecutive vec4 = one row) -> uniform ti/rw
        const int ti = __ldg(at + row0 + (v >> 5));
        const uint32_t rw = s_rw[ti];

        int4 nj = nl[v];

        int j0 = (nj.x < 0) ? NALL : nj.x;
        int j1 = (nj.y < 0) ? NALL : nj.y;
        int j2 = (nj.z < 0) ? NALL : nj.z;
        int j3 = (nj.w < 0) ? NALL : nj.w;

        uint32_t w0 = s_nib[j0 >> 3];
        uint32_t w1 = s_nib[j1 >> 3];
        uint32_t w2 = s_nib[j2 >> 3];
        uint32_t w3 = s_nib[j3 >> 3];

        int t0 = (w0 >> ((j0 & 7) << 2)) & 15;
        int t1 = (w1 >> ((j1 & 7) << 2)) & 15;
        int t2 = (w2 >> ((j2 & 7) << 2)) & 15;
        int t3 = (w3 >> ((j3 & 7) << 2)) & 15;

        float4 r;
        r.x = ((rw >> t0) & 1u) ? 1.0f : 0.0f;
        r.y = ((rw >> t1) & 1u) ? 1.0f : 0.0f;
        r.z = ((rw >> t2) & 1u) ? 1.0f : 0.0f;
        r.w = ((rw >> t3) & 1u) ? 1.0f : 0.0f;

        ob[v] = r;
    }
}

extern "C" void kernel_launch(void* const* d_in, const int* in_sizes, int n_in,
                              void* d_out, int out_size)
{
    const int4*  nlist4 = (const int4*) d_in[0];
    const int*   atype  = (const int*)  d_in[1];
    const float* tmask  = (const float*)d_in[2];
    // d_in[3] = ntypes scalar (8, baked into constants)

    float4* out4 = (float4*)d_out;

    pack_kernel<<<NF * WORDS / 256, 256>>>(atype);
    mask_kernel<<<BLOCKS_B, THREADS_B>>>(nlist4, atype, tmask, out4);
}

// round 4
// speedup vs baseline: 1.7732x; 1.1317x over previous
#include <cuda_runtime.h>
#include <cuda_bf16.h>
#include <cstdint>

// PairExcludeMask: out[f,i,n] = type_mask[ atype[f,i]*9 + tj ]
//   tj = (nlist[f,i,n] == -1) ? 8 : atype[f, nlist[f,i,n]]
//
// Kernel 1 packs atype into 4-bit nibbles (one 16KB table per frame).
// Kernel 2: one warp per row. Row word rw[ti] (bit tj = mask!=0) is
// warp-uniform; if rw passes every type (or excludes every type) the whole
// row is written as a constant WITHOUT reading nlist or gathering. Only
// "interesting" rows take the gather path (random LDS into the nibble table).
//
// Shapes fixed by dataset:
//   nlist [4,16384,128] i32, atype_ext [4,32768] i32, type_mask [81] f32,
//   out [4,16384,128] f32

static constexpr int NF     = 4;
static constexpr int NLOC   = 16384;
static constexpr int NNEI   = 128;
static constexpr int NALL   = 32768;
static constexpr int NTYPES = 8;
static constexpr int TM1    = NTYPES + 1;          // 9
static constexpr uint32_t FULL = (1u << TM1) - 1;  // 0x1FF

static constexpr int WORDS   = NALL / 8;           // 4096 packed words / frame
static constexpr int WORDS_P = WORDS + 8;          // + virtual-atom word + pad

__device__ __align__(16) uint32_t g_pack[NF][WORDS_P];

// ---------------- kernel 1: pack types to nibbles ----------------
__global__ __launch_bounds__(256)
void pack_kernel(const int* __restrict__ atype)
{
    int idx = blockIdx.x * 256 + threadIdx.x;      // 0 .. NF*WORDS-1
    int f   = idx >> 12;                           // / WORDS (4096)
    int wi  = idx & (WORDS - 1);
    const int4* __restrict__ at4 = (const int4*)(atype + f * NALL);
    int4 a = at4[wi * 2];
    int4 b = at4[wi * 2 + 1];
    uint32_t p = (uint32_t)a.x        | ((uint32_t)a.y << 4)
               | ((uint32_t)a.z << 8) | ((uint32_t)a.w << 12)
               | ((uint32_t)b.x << 16)| ((uint32_t)b.y << 20)
               | ((uint32_t)b.z << 24)| ((uint32_t)b.w << 28);
    g_pack[f][wi] = p;
    if (wi == 0) {                                 // virtual atom j == NALL
        g_pack[f][WORDS] = (uint32_t)NTYPES;       // nibble 0 = type 8
        #pragma unroll
        for (int k = 1; k < 8; ++k) g_pack[f][WORDS + k] = 0;
    }
}

// ---------------- kernel 2: stream the mask ----------------
static constexpr int THREADS_B = 512;
static constexpr int BPF       = 128;                      // blocks per frame
static constexpr int ROWS_PB   = NLOC / BPF;               // 128
static constexpr int ROW_VEC   = NNEI / 4;                 // 32 vec4 per row
static constexpr int VEC_PB    = ROWS_PB * ROW_VEC;        // 4096
static constexpr int ITERS     = VEC_PB / THREADS_B;       // 8
static constexpr int BLOCKS_B  = NF * BPF;                 // 512

__global__ __launch_bounds__(THREADS_B)
void mask_kernel(const int4* __restrict__ nlist4,
                 const int*  __restrict__ atype,
                 const float* __restrict__ tmask,
                 float4* __restrict__ out4)
{
    __shared__ uint32_t s_nib[WORDS_P];            // 16.4 KB nibble table
    __shared__ uint32_t s_rw[16];                  // per-center-type row word

    const int tid  = threadIdx.x;
    const int f    = blockIdx.x >> 7;              // / BPF
    const int row0 = (blockIdx.x & (BPF - 1)) * ROWS_PB;

    // coalesced 16-byte copy of the packed nibble table from L2
    {
        const uint4* __restrict__ src = (const uint4*)g_pack[f];
        uint4* dst = (uint4*)s_nib;
        #pragma unroll
        for (int k = tid; k < WORDS_P / 4; k += THREADS_B)
            dst[k] = src[k];
    }
    // rw[ti] bit tj = (type_mask[ti*9+tj] != 0)
    if (tid < TM1) {
        uint32_t w = 0;
        #pragma unroll
        for (int tj = 0; tj < TM1; ++tj)
            w |= (tmask[tid * TM1 + tj] != 0.0f ? 1u : 0u) << tj;
        s_rw[tid] = w;
    }
    __syncthreads();

    const int* __restrict__ at = atype + f * NALL;
    const size_t base = ((size_t)f * NLOC + row0) * ROW_VEC;
    const int4*  __restrict__ nl = nlist4 + base;
    float4*      __restrict__ ob = out4  + base;

    #pragma unroll
    for (int k = 0; k < ITERS; ++k) {
        const int v = tid + k * THREADS_B;
        // one warp covers one row (32 consecutive vec4) -> warp-uniform ti/rw
        const int ti = __ldg(at + row0 + (v >> 5));
        const uint32_t rw = s_rw[ti];

        if (rw == FULL) {                          // row passes every type
            ob[v] = make_float4(1.0f, 1.0f, 1.0f, 1.0f);
            continue;
        }
        if (rw == 0u) {                            // row excludes every type
            ob[v] = make_float4(0.0f, 0.0f, 0.0f, 0.0f);
            continue;
        }

        int4 nj = nl[v];

        // -1 -> NALL via unsigned min (single IMNMX)
        uint32_t j0 = min((uint32_t)nj.x, (uint32_t)NALL);
        uint32_t j1 = min((uint32_t)nj.y, (uint32_t)NALL);
        uint32_t j2 = min((uint32_t)nj.z, (uint32_t)NALL);
        uint32_t j3 = min((uint32_t)nj.w, (uint32_t)NALL);

        uint32_t w0 = s_nib[j0 >> 3];
        uint32_t w1 = s_nib[j1 >> 3];
        uint32_t w2 = s_nib[j2 >> 3];
        uint32_t w3 = s_nib[j3 >> 3];

        int t0 = (w0 >> ((j0 & 7) << 2)) & 15;
        int t1 = (w1 >> ((j1 & 7) << 2)) & 15;
        int t2 = (w2 >> ((j2 & 7) << 2)) & 15;
        int t3 = (w3 >> ((j3 & 7) << 2)) & 15;

        float4 r;
        r.x = ((rw >> t0) & 1u) ? 1.0f : 0.0f;
        r.y = ((rw >> t1) & 1u) ? 1.0f : 0.0f;
        r.z = ((rw >> t2) & 1u) ? 1.0f : 0.0f;
        r.w = ((rw >> t3) & 1u) ? 1.0f : 0.0f;

        ob[v] = r;
    }
}

extern "C" void kernel_launch(void* const* d_in, const int* in_sizes, int n_in,
                              void* d_out, int out_size)
{
    const int4*  nlist4 = (const int4*) d_in[0];
    const int*   atype  = (const int*)  d_in[1];
    const float* tmask  = (const float*)d_in[2];
    // d_in[3] = ntypes scalar (8, baked into constants)

    float4* out4 = (float4*)d_out;

    pack_kernel<<<NF * WORDS / 256, 256>>>(atype);
    mask_kernel<<<BLOCKS_B, THREADS_B>>>(nlist4, atype, tmask, out4);
}

// round 5
// speedup vs baseline: 1.8221x; 1.0276x over previous
#include <cuda_runtime.h>
#include <cuda_bf16.h>
#include <cstdint>

// PairExcludeMask: out[f,i,n] = type_mask[ atype[f,i]*9 + tj ]
//   tj = (nlist[f,i,n] == -1) ? 8 : atype[f, nlist[f,i,n]]
//
// Kernel 1 packs atype into a 4-bit-per-atom table (16KB per frame).
// Kernel 2 is software-pipelined in 3 passes per thread to maximize MLP:
//   pass A: 4 independent row-word lookups (LDS)
//   pass B: 4 independent predicated nlist loads (LDG, front-batched)
//   pass C: gather nibbles from the SMEM table + store
// Rows whose row-word is all-ones / all-zeros skip the load+gather entirely.

static constexpr int NF     = 4;
static constexpr int NLOC   = 16384;
static constexpr int NNEI   = 128;
static constexpr int NALL   = 32768;
static constexpr int NTYPES = 8;
static constexpr int TM1    = NTYPES + 1;          // 9
static constexpr uint32_t FULL = (1u << TM1) - 1;  // 0x1FF

static constexpr int WORDS   = NALL / 8;           // 4096 packed words / frame
static constexpr int WORDS_P = WORDS + 8;          // + virtual-atom word + pad

__device__ __align__(16) uint32_t g_pack[NF][WORDS_P];

// ---------------- kernel 1: pack types to nibbles ----------------
__global__ __launch_bounds__(256)
void pack_kernel(const int* __restrict__ atype)
{
    int idx = blockIdx.x * 256 + threadIdx.x;      // 0 .. NF*WORDS-1
    int f   = idx >> 12;                           // / WORDS (4096)
    int wi  = idx & (WORDS - 1);
    const int4* __restrict__ at4 = (const int4*)(atype + f * NALL);
    int4 a = at4[wi * 2];
    int4 b = at4[wi * 2 + 1];
    uint32_t p = (uint32_t)a.x        | ((uint32_t)a.y << 4)
               | ((uint32_t)a.z << 8) | ((uint32_t)a.w << 12)
               | ((uint32_t)b.x << 16)| ((uint32_t)b.y << 20)
               | ((uint32_t)b.z << 24)| ((uint32_t)b.w << 28);
    g_pack[f][wi] = p;
    if (wi == 0) {                                 // virtual atom j == NALL
        g_pack[f][WORDS] = (uint32_t)NTYPES;       // nibble 0 = type 8
        #pragma unroll
        for (int k = 1; k < 8; ++k) g_pack[f][WORDS + k] = 0;
    }
}

// ---------------- kernel 2: stream the mask ----------------
static constexpr int THREADS_B = 512;
static constexpr int BPF       = 256;                      // blocks per frame
static constexpr int ROWS_PB   = NLOC / BPF;               // 64 rows / block
static constexpr int ROW_VEC   = NNEI / 4;                 // 32 vec4 per row
static constexpr int VEC_PB    = ROWS_PB * ROW_VEC;        // 2048
static constexpr int ITERS     = VEC_PB / THREADS_B;       // 4
static constexpr int BLOCKS_B  = NF * BPF;                 // 1024

__global__ __launch_bounds__(THREADS_B)
void mask_kernel(const int4* __restrict__ nlist4,
                 const int*  __restrict__ atype,
                 const float* __restrict__ tmask,
                 float4* __restrict__ out4)
{
    __shared__ uint32_t s_nib[WORDS_P];            // 16.4 KB nibble table
    __shared__ uint32_t s_rw[16];                  // per-type row word
    __shared__ uint32_t s_rowrw[ROWS_PB];          // per-row row word

    const int tid  = threadIdx.x;
    const int f    = blockIdx.x >> 8;              // / BPF
    const int row0 = (blockIdx.x & (BPF - 1)) * ROWS_PB;

    // coalesced 16-byte copy of the packed nibble table from L2
    {
        const uint4* __restrict__ src = (const uint4*)g_pack[f];
        uint4* dst = (uint4*)s_nib;
        #pragma unroll
        for (int k = tid; k < WORDS_P / 4; k += THREADS_B)
            dst[k] = src[k];
    }
    // rw[ti] bit tj = (type_mask[ti*9+tj] != 0)
    if (tid < TM1) {
        uint32_t w = 0;
        #pragma unroll
        for (int tj = 0; tj < TM1; ++tj)
            w |= (tmask[tid * TM1 + tj] != 0.0f ? 1u : 0u) << tj;
        s_rw[tid] = w;
    }
    __syncthreads();
    if (tid < ROWS_PB)
        s_rowrw[tid] = s_rw[__ldg(atype + f * NALL + row0 + tid)];
    __syncthreads();

    const size_t base = ((size_t)f * NLOC + row0) * ROW_VEC;
    const int4*  __restrict__ nl = nlist4 + base;
    float4*      __restrict__ ob = out4  + base;

    // ---- pass A: independent row-word lookups (one row per warp) ----
    uint32_t rw[ITERS];
    #pragma unroll
    for (int k = 0; k < ITERS; ++k)
        rw[k] = s_rowrw[(tid + k * THREADS_B) >> 5];

    // ---- pass B: independent (predicated) nlist loads, front-batched ----
    int4 nj[ITERS];
    #pragma unroll
    for (int k = 0; k < ITERS; ++k) {
        const uint32_t w = rw[k];
        if (w != FULL && w != 0u)
            nj[k] = nl[tid + k * THREADS_B];
    }

    // ---- pass C: gather + store ----
    #pragma unroll
    for (int k = 0; k < ITERS; ++k) {
        const int v = tid + k * THREADS_B;
        const uint32_t w = rw[k];

        if (w == FULL) { ob[v] = make_float4(1.f, 1.f, 1.f, 1.f); continue; }
        if (w == 0u)   { ob[v] = make_float4(0.f, 0.f, 0.f, 0.f); continue; }

        uint32_t j0 = min((uint32_t)nj[k].x, (uint32_t)NALL);
        uint32_t j1 = min((uint32_t)nj[k].y, (uint32_t)NALL);
        uint32_t j2 = min((uint32_t)nj[k].z, (uint32_t)NALL);
        uint32_t j3 = min((uint32_t)nj[k].w, (uint32_t)NALL);

        uint32_t w0 = s_nib[j0 >> 3];
        uint32_t w1 = s_nib[j1 >> 3];
        uint32_t w2 = s_nib[j2 >> 3];
        uint32_t w3 = s_nib[j3 >> 3];

        int t0 = (w0 >> ((j0 & 7) << 2)) & 15;
        int t1 = (w1 >> ((j1 & 7) << 2)) & 15;
        int t2 = (w2 >> ((j2 & 7) << 2)) & 15;
        int t3 = (w3 >> ((j3 & 7) << 2)) & 15;

        float4 r;
        r.x = ((w >> t0) & 1u) ? 1.0f : 0.0f;
        r.y = ((w >> t1) & 1u) ? 1.0f : 0.0f;
        r.z = ((w >> t2) & 1u) ? 1.0f : 0.0f;
        r.w = ((w >> t3) & 1u) ? 1.0f : 0.0f;

        ob[v] = r;
    }
}

extern "C" void kernel_launch(void* const* d_in, const int* in_sizes, int n_in,
                              void* d_out, int out_size)
{
    const int4*  nlist4 = (const int4*) d_in[0];
    const int*   atype  = (const int*)  d_in[1];
    const float* tmask  = (const float*)d_in[2];
    // d_in[3] = ntypes scalar (8, baked into constants)

    float4* out4 = (float4*)d_out;

    pack_kernel<<<NF * WORDS / 256, 256>>>(atype);
    mask_kernel<<<BLOCKS_B, THREADS_B>>>(nlist4, atype, tmask, out4);
}